// round 17
// baseline (speedup 1.0000x reference)
#include <cuda_runtime.h>
#include <math.h>

// ---------------- scratch (static device globals) ---------------------------
__device__ float g_xg_f[16*128*1024];
__device__ float g_xg_b[16*128*1024];
__device__ float g_Wsl[2*8*256*128];   // per (dir,slice): k-major [256][128]
__device__ float g_hf [16*128*256];
__device__ float g_hb [16*128*256];
__device__ float g_o  [16*128*256];
__device__ float g_u  [2048*128];
__device__ float g_v  [2048*128];
__device__ float g_a  [2048*128];
__device__ float g_cb [2048*128];
__device__ float g_crf[16];
__device__ float g_selpart[512];

// ---------------- generic 64x64 SGEMM: C = op(A) @ W^T (+bias)(relu) --------
// amode: 0 = A[row*lda+k]; 1 = word_emb[tokens[row]*256+k];
//        2 = k<256 ? g_o[row*256+k] : bio_emb[bio_gold[row]*64+(k-256)]
__global__ __launch_bounds__(256) void gemm_kernel(
    int K, int amode,
    const float* __restrict__ A, int lda,
    const int*   __restrict__ tokens,
    const float* __restrict__ word_emb,
    const int*   __restrict__ bio_gold,
    const float* __restrict__ bio_emb,
    const float* __restrict__ W, int ldw,
    const float* __restrict__ bias, int do_relu,
    float* __restrict__ C, int ldc)
{
    __shared__ __align__(16) float As[16][68];
    __shared__ __align__(16) float Bs[16][68];
    int tid = threadIdx.x;
    int tx = tid & 15, ty = tid >> 4;
    int row0 = blockIdx.y * 64, col0 = blockIdx.x * 64;
    float acc[4][4];
#pragma unroll
    for (int i = 0; i < 4; ++i)
#pragma unroll
        for (int j = 0; j < 4; ++j) acc[i][j] = 0.f;

    for (int k0 = 0; k0 < K; k0 += 16) {
#pragma unroll
        for (int l = 0; l < 4; ++l) {
            int e = tid + l * 256;
            int m = e >> 4, kk = e & 15;
            int row = row0 + m, k = k0 + kk;
            float v;
            if (amode == 0)      v = A[row * lda + k];
            else if (amode == 1) v = word_emb[tokens[row] * 256 + k];
            else                 v = (k < 256) ? g_o[row * 256 + k]
                                               : bio_emb[bio_gold[row] * 64 + (k - 256)];
            As[kk][m] = v;
            Bs[kk][m] = W[(col0 + m) * ldw + k];
        }
        __syncthreads();
#pragma unroll
        for (int kk = 0; kk < 16; ++kk) {
            float4 a4 = *(const float4*)&As[kk][ty << 2];
            float4 b4 = *(const float4*)&Bs[kk][tx << 2];
            acc[0][0]=fmaf(a4.x,b4.x,acc[0][0]); acc[0][1]=fmaf(a4.x,b4.y,acc[0][1]);
            acc[0][2]=fmaf(a4.x,b4.z,acc[0][2]); acc[0][3]=fmaf(a4.x,b4.w,acc[0][3]);
            acc[1][0]=fmaf(a4.y,b4.x,acc[1][0]); acc[1][1]=fmaf(a4.y,b4.y,acc[1][1]);
            acc[1][2]=fmaf(a4.y,b4.z,acc[1][2]); acc[1][3]=fmaf(a4.y,b4.w,acc[1][3]);
            acc[2][0]=fmaf(a4.z,b4.x,acc[2][0]); acc[2][1]=fmaf(a4.z,b4.y,acc[2][1]);
            acc[2][2]=fmaf(a4.z,b4.z,acc[2][2]); acc[2][3]=fmaf(a4.z,b4.w,acc[2][3]);
            acc[3][0]=fmaf(a4.w,b4.x,acc[3][0]); acc[3][1]=fmaf(a4.w,b4.y,acc[3][1]);
            acc[3][2]=fmaf(a4.w,b4.z,acc[3][2]); acc[3][3]=fmaf(a4.w,b4.w,acc[3][3]);
        }
        __syncthreads();
    }
#pragma unroll
    for (int i = 0; i < 4; ++i) {
        int row = row0 + (ty << 2) + i;
#pragma unroll
        for (int j = 0; j < 4; ++j) {
            int col = col0 + (tx << 2) + j;
            float v = acc[i][j];
            if (bias) v += bias[col];
            if (do_relu) v = fmaxf(v, 0.f);
            C[row * ldc + col] = v;
        }
    }
}

// ---------------- prep: W_hh -> per-(dir,slice) k-major slices --------------
// g_Wsl[(dir*8+s)*32768 + k*128 + (g*32+u)] = W[(g*256 + s*32 + u)*256 + k]
__global__ __launch_bounds__(256) void prep_kernel(
    const float* __restrict__ Wf, const float* __restrict__ Wb)
{
    __shared__ float tile[32][33];
    int dir = blockIdx.z;
    const float* W = dir ? Wb : Wf;
    int R0 = blockIdx.x * 32;
    int k0 = blockIdx.y * 32;
    int g = R0 >> 8;
    int s = (R0 >> 5) & 7;
    int tx = threadIdx.x & 31, ty = threadIdx.x >> 5;
#pragma unroll
    for (int l = 0; l < 4; ++l)
        tile[ty + 8*l][tx] = W[(R0 + ty + 8*l) * 256 + k0 + tx];
    __syncthreads();
    float* dst = g_Wsl + ((dir*8 + s) << 15);
#pragma unroll
    for (int l = 0; l < 4; ++l)
        dst[(k0 + ty + 8*l) * 128 + g*32 + tx] = tile[tx][ty + 8*l];
}

// ---------------- DSMEM / mbarrier helpers ----------------------------------
__device__ __forceinline__ unsigned smem_u32(const void* p) {
    unsigned a;
    asm("{ .reg .u64 t; cvta.to.shared.u64 t, %1; cvt.u32.u64 %0, t; }"
        : "=r"(a) : "l"(p));
    return a;
}
__device__ __forceinline__ unsigned cta_rank() {
    unsigned r; asm("mov.u32 %0, %%cluster_ctarank;" : "=r"(r)); return r;
}
__device__ __forceinline__ void dsmem_st(unsigned laddr, int rank, float v) {
    unsigned raddr;
    asm volatile("mapa.shared::cluster.u32 %0, %1, %2;"
                 : "=r"(raddr) : "r"(laddr), "r"(rank));
    asm volatile("st.shared::cluster.f32 [%0], %1;"
                 :: "r"(raddr), "f"(v) : "memory");
}
__device__ __forceinline__ void mbar_arrive_remote(unsigned local_mbar, int rank) {
    unsigned raddr;
    asm volatile("mapa.shared::cluster.u32 %0, %1, %2;"
                 : "=r"(raddr) : "r"(local_mbar), "r"(rank));
    asm volatile("mbarrier.arrive.release.cluster.shared::cluster.b64 _, [%0];"
                 :: "r"(raddr) : "memory");
}
__device__ __forceinline__ void mbar_wait_cluster(unsigned mbar, unsigned parity) {
    asm volatile(
        "{\n\t"
        ".reg .pred P;\n\t"
        "WAIT_%=:\n\t"
        "mbarrier.try_wait.parity.acquire.cluster.shared::cta.b64 P, [%0], %1, 0x989680;\n\t"
        "@P bra.uni DONE_%=;\n\t"
        "bra.uni WAIT_%=;\n\t"
        "DONE_%=:\n\t"
        "}"
        :: "r"(mbar), "r"(parity) : "memory");
}

// ---------------- BiLSTM: 4-batch pipelined clusters ------------------------
// 8 clusters x 8 CTAs = 64 CTAs. Cluster cl: dir = cl>>2, batches
// (cl&3)*4 + s for slot s=0..3 (all same dir -> shared weights).
// CTA (rank=slice) owns 32 units per slot. 512 threads = 128 rows x 4 k-quads;
// weights register-resident (64/thread). Slots processed round-robin with one
// mbarrier per slot: slot s's sync round-trip hides behind other slots' work.
__global__ void __cluster_dims__(8,1,1) __launch_bounds__(512) lstm_cluster_kernel()
{
    int slice = cta_rank();
    int cl  = blockIdx.x >> 3;          // 0..7
    int dir = cl >> 2, bquad = cl & 3;
    const float* xg = dir ? g_xg_b : g_xg_f;
    float* hout     = dir ? g_hb : g_hf;
    __shared__ __align__(16) float h_s[2*4*256];   // [phase][slot][256]
    __shared__ float part[2*4*132];                // [pbuf][q][132]
    __shared__ __align__(8) unsigned long long mbar[4];
    int tid = threadIdx.x;
    int r = tid & 127, q = tid >> 7;

    // register-resident weights: row r, k-range q*64..q*64+63 (coalesced LDG)
    const float* gw = g_Wsl + ((dir*8 + slice) << 15);
    float wreg[64];
#pragma unroll
    for (int kl = 0; kl < 64; ++kl)
        wreg[kl] = gw[((q << 6) + kl) * 128 + r];

    // tail role: warp ts handles slot ts (unit tu); cell state lives there
    int ts = tid >> 5, tu = tid & 31;
    int tb = (bquad << 2) + ts;         // batch for slot ts (valid ts<4)
    unsigned hs_base = smem_u32(h_s);
    unsigned mb_base = smem_u32(mbar);
    float cst = 0.f;

    for (int i = tid; i < 2048; i += 512) h_s[i] = 0.f;
    if (tid < 4)
        asm volatile("mbarrier.init.shared.b64 [%0], %1;"
                     :: "r"(mb_base + tid*8), "r"(8u) : "memory");
    __syncthreads();
    asm volatile("barrier.cluster.arrive.aligned;" ::: "memory");
    asm volatile("barrier.cluster.wait.aligned;"   ::: "memory");

    for (int step = 0; step < 128; ++step) {
        int t = dir ? (127 - step) : step;
        int phase = step & 1;
        float xv0 = 0.f, xv1 = 0.f, xv2 = 0.f, xv3 = 0.f;
        if (ts < 4) {   // prefetch this slot's xg (consumed in tail)
            const float* xrow = xg + (((tb << 7) + t) << 10) + (slice << 5) + tu;
            xv0 = xrow[0]; xv1 = xrow[256]; xv2 = xrow[512]; xv3 = xrow[768];
        }
#pragma unroll
        for (int s = 0; s < 4; ++s) {
            if (step) mbar_wait_cluster(mb_base + s*8, (step - 1) & 1);
            const float4* hp4 = (const float4*)&h_s[(phase << 10) + (s << 8) + (q << 6)];
            float a0 = 0.f, a1 = 0.f, a2 = 0.f, a3 = 0.f;
#pragma unroll
            for (int k4 = 0; k4 < 16; k4 += 4) {
                float4 hA = hp4[k4],   hB = hp4[k4+1];
                float4 hC = hp4[k4+2], hD = hp4[k4+3];
                a0 = fmaf(wreg[4*k4+ 0], hA.x, a0); a0 = fmaf(wreg[4*k4+ 1], hA.y, a0);
                a0 = fmaf(wreg[4*k4+ 2], hA.z, a0); a0 = fmaf(wreg[4*k4+ 3], hA.w, a0);
                a1 = fmaf(wreg[4*k4+ 4], hB.x, a1); a1 = fmaf(wreg[4*k4+ 5], hB.y, a1);
                a1 = fmaf(wreg[4*k4+ 6], hB.z, a1); a1 = fmaf(wreg[4*k4+ 7], hB.w, a1);
                a2 = fmaf(wreg[4*k4+ 8], hC.x, a2); a2 = fmaf(wreg[4*k4+ 9], hC.y, a2);
                a2 = fmaf(wreg[4*k4+10], hC.z, a2); a2 = fmaf(wreg[4*k4+11], hC.w, a2);
                a3 = fmaf(wreg[4*k4+12], hD.x, a3); a3 = fmaf(wreg[4*k4+13], hD.y, a3);
                a3 = fmaf(wreg[4*k4+14], hD.z, a3); a3 = fmaf(wreg[4*k4+15], hD.w, a3);
            }
            part[(s & 1)*528 + q*132 + r] = (a0 + a1) + (a2 + a3);
            __syncthreads();
            if (ts == s) {   // warp s: tail for slot s (overlaps next slot's k-loop)
                const float* pb = &part[(s & 1)*528];
                float g0 = xv0, g1 = xv1, g2 = xv2, g3 = xv3;
#pragma unroll
                for (int qq = 0; qq < 4; ++qq) {
                    const float* p = pb + qq*132;
                    g0 += p[tu]; g1 += p[32 + tu]; g2 += p[64 + tu]; g3 += p[96 + tu];
                }
                float si = 1.f / (1.f + expf(-g0));
                float sf = 1.f / (1.f + expf(-g1));
                float so = 1.f / (1.f + expf(-g3));
                cst = sf * cst + si * tanhf(g2);
                float h = so * tanhf(cst);
                hout[(((tb << 7) + t) << 8) + (slice << 5) + tu] = h;
                unsigned dsta = hs_base +
                    ((((phase ^ 1) << 10) + (s << 8) + (slice << 5) + tu) << 2);
#pragma unroll
                for (int rk = 0; rk < 8; ++rk) dsmem_st(dsta, rk, h);
                __syncwarp();
                if (tu < 8) mbar_arrive_remote(mb_base + s*8, tu);
            }
        }
    }
    asm volatile("barrier.cluster.arrive.aligned;" ::: "memory");
    asm volatile("barrier.cluster.wait.aligned;"   ::: "memory");
}

// ---------------- o = 0.5*(h_f + h_b) ---------------------------------------
__global__ void combine_kernel() {
    int i = blockIdx.x * blockDim.x + threadIdx.x;
    float4 f = ((const float4*)g_hf)[i];
    float4 b = ((const float4*)g_hb)[i];
    float4 o;
    o.x = 0.5f*(f.x+b.x); o.y = 0.5f*(f.y+b.y);
    o.z = 0.5f*(f.z+b.z); o.w = 0.5f*(f.w+b.w);
    ((float4*)g_o)[i] = o;
}

// ---------------- CRF: emi projection + forward algorithm -------------------
__global__ __launch_bounds__(128) void crf_kernel(
    const int* __restrict__ tokens, const int* __restrict__ bio_gold,
    const float* __restrict__ emi_W, const float* __restrict__ emi_b,
    const float* __restrict__ crf_start, const float* __restrict__ crf_end,
    const float* __restrict__ crf_trans)
{
    int b = blockIdx.x;
    __shared__ float emi_s[128][3];
    __shared__ float Wsh[768];
    __shared__ float bsh[3], st[3], en[3], tr[9];
    __shared__ float msk[128];
    __shared__ int   bio_s[128];
    int tid = threadIdx.x;
    for (int e = tid; e < 768; e += 128) Wsh[e] = emi_W[e];
    if (tid < 3) { bsh[tid]=emi_b[tid]; st[tid]=crf_start[tid]; en[tid]=crf_end[tid]; }
    if (tid < 9) tr[tid] = crf_trans[tid];
    bio_s[tid] = bio_gold[b * 128 + tid];
    msk[tid]   = (tokens[b * 128 + tid] != 0) ? 1.f : 0.f;
    __syncthreads();
    {
        const float4* orow = (const float4*)(g_o + (b * 128 + tid) * 256);
        float a0=0.f, a1=0.f, a2=0.f;
#pragma unroll 4
        for (int k = 0; k < 64; ++k) {
            float4 ov = orow[k];
            const float* w0 = &Wsh[4*k];
            const float* w1 = &Wsh[256 + 4*k];
            const float* w2 = &Wsh[512 + 4*k];
            a0 += ov.x*w0[0] + ov.y*w0[1] + ov.z*w0[2] + ov.w*w0[3];
            a1 += ov.x*w1[0] + ov.y*w1[1] + ov.z*w1[2] + ov.w*w1[3];
            a2 += ov.x*w2[0] + ov.y*w2[1] + ov.z*w2[2] + ov.w*w2[3];
        }
        emi_s[tid][0] = a0 + bsh[0];
        emi_s[tid][1] = a1 + bsh[1];
        emi_s[tid][2] = a2 + bsh[2];
    }
    __syncthreads();
    if (tid < 32) {
        float score = 0.f;
        if (tid < 3) score = st[tid] + emi_s[0][tid];
        for (int t = 1; t < 128; ++t) {
            float s0 = __shfl_sync(0xffffffffu, score, 0);
            float s1 = __shfl_sync(0xffffffffu, score, 1);
            float s2 = __shfl_sync(0xffffffffu, score, 2);
            if (tid < 3) {
                float x0 = s0 + tr[tid];
                float x1 = s1 + tr[3 + tid];
                float x2 = s2 + tr[6 + tid];
                float mx = fmaxf(x0, fmaxf(x1, x2));
                float l  = mx + logf(expf(x0-mx) + expf(x1-mx) + expf(x2-mx))
                           + emi_s[t][tid];
                if (msk[t] > 0.f) score = l;
            }
        }
        float f0 = __shfl_sync(0xffffffffu, score, 0) + en[0];
        float f1 = __shfl_sync(0xffffffffu, score, 1) + en[1];
        float f2 = __shfl_sync(0xffffffffu, score, 2) + en[2];
        if (tid == 0) {
            float mx  = fmaxf(f0, fmaxf(f1, f2));
            float den = mx + logf(expf(f0-mx) + expf(f1-mx) + expf(f2-mx));
            float num = st[bio_s[0]] + emi_s[0][bio_s[0]];
            int cnt = 0;
            for (int t = 0; t < 128; ++t) if (msk[t] > 0.f) ++cnt;
            for (int t = 1; t < 128; ++t)
                num += (tr[bio_s[t-1]*3 + bio_s[t]] + emi_s[t][bio_s[t]]) * msk[t];
            int se = cnt - 1; if (se < 0) se = 0;
            num += en[bio_s[se]];
            g_crf[b] = num - den;
        }
    }
}

// ---------------- selection head: logits + masked BCE partial sums ----------
__global__ __launch_bounds__(256) void sel_kernel(
    const float* __restrict__ rel_emb, const float* __restrict__ Y,
    const int* __restrict__ tokens)
{
    __shared__ float a_s [128*33];
    __shared__ float cb_s[128*17];
    __shared__ float rel_s[128*25];
    __shared__ float mI[16], mJ[32], red[8];
    int b  = blockIdx.y;
    int i0 = (blockIdx.x >> 2) * 16, j0 = (blockIdx.x & 3) * 32;
    int tid = threadIdx.x;
    for (int e = tid; e < 32*128; e += 256) {
        int j = e >> 7, h = e & 127;
        a_s[h*33 + j] = g_a[(b*128 + j0 + j)*128 + h];
    }
    for (int e = tid; e < 16*128; e += 256) {
        int i = e >> 7, h = e & 127;
        cb_s[h*17 + i] = g_cb[(b*128 + i0 + i)*128 + h];
    }
    for (int e = tid; e < 25*128; e += 256) {
        int r = e >> 7, h = e & 127;
        rel_s[h*25 + r] = rel_emb[r*128 + h];
    }
    if (tid < 32) mJ[tid] = (tokens[b*128 + j0 + tid] != 0) ? 1.f : 0.f;
    if (tid < 16) mI[tid] = (tokens[b*128 + i0 + tid] != 0) ? 1.f : 0.f;
    __syncthreads();

    int j = tid & 31, ia = tid >> 5, ib = ia + 8;
    float acc0[25], acc1[25];
#pragma unroll
    for (int r = 0; r < 25; ++r) { acc0[r] = 0.f; acc1[r] = 0.f; }
    for (int h = 0; h < 128; ++h) {
        float av = a_s[h*33 + j];
        float u0 = fmaxf(av + cb_s[h*17 + ia], 0.f);
        float u1 = fmaxf(av + cb_s[h*17 + ib], 0.f);
        const float* rp = &rel_s[h*25];
#pragma unroll
        for (int r = 0; r < 25; ++r) {
            float rv = rp[r];
            acc0[r] = fmaf(u0, rv, acc0[r]);
            acc1[r] = fmaf(u1, rv, acc1[r]);
        }
    }
    float mj = mJ[j];
    float m0 = mI[ia]*mj, m1 = mI[ib]*mj;
    int gi0 = b*128 + i0 + ia, gi1 = b*128 + i0 + ib;
    float tsum = 0.f;
#pragma unroll
    for (int r = 0; r < 25; ++r) {
        float l = acc0[r];
        float y = Y[(gi0*25 + r)*128 + j0 + j];
        tsum += m0 * (fmaxf(l,0.f) - l*y + log1pf(expf(-fabsf(l))));
        l = acc1[r];
        y = Y[(gi1*25 + r)*128 + j0 + j];
        tsum += m1 * (fmaxf(l,0.f) - l*y + log1pf(expf(-fabsf(l))));
    }
    for (int off = 16; off; off >>= 1)
        tsum += __shfl_down_sync(0xffffffffu, tsum, off);
    if ((tid & 31) == 0) red[tid >> 5] = tsum;
    __syncthreads();
    if (tid < 8) {
        float v2 = red[tid];
        for (int off = 4; off; off >>= 1)
            v2 += __shfl_down_sync(0xffu, v2, off);
        if (tid == 0) g_selpart[blockIdx.y*32 + blockIdx.x] = v2;
    }
}

// ---------------- final deterministic reduction ------------------------------
__global__ __launch_bounds__(512) void final_kernel(const int* __restrict__ tokens,
                                                    float* __restrict__ out)
{
    __shared__ float sh[512];
    __shared__ int csh[512];
    int tid = threadIdx.x;
    int cnt = 0;
    for (int e = tid; e < 2048; e += 512) cnt += (tokens[e] != 0);
    sh[tid] = g_selpart[tid];
    csh[tid] = cnt;
    __syncthreads();
    for (int off = 256; off; off >>= 1) {
        if (tid < off) { sh[tid] += sh[tid+off]; csh[tid] += csh[tid+off]; }
        __syncthreads();
    }
    if (tid == 0) {
        float crf = 0.f;
        for (int b = 0; b < 16; ++b) crf += g_crf[b];
        out[0] = -(crf / 16.f) + sh[0] / (float)csh[0];
    }
}

// ---------------- launch -----------------------------------------------------
extern "C" void kernel_launch(void* const* d_in, const int* in_sizes, int n_in,
                              void* d_out, int out_size)
{
    const int*   tokens    = (const int*)  d_in[0];
    const int*   bio_gold  = (const int*)  d_in[1];
    const float* sel_gold  = (const float*)d_in[2];
    const float* word_emb  = (const float*)d_in[3];
    const float* W_ih_f    = (const float*)d_in[4];
    const float* W_hh_f    = (const float*)d_in[5];
    const float* b_f       = (const float*)d_in[6];
    const float* W_ih_b    = (const float*)d_in[7];
    const float* W_hh_b    = (const float*)d_in[8];
    const float* b_b       = (const float*)d_in[9];
    const float* emi_W     = (const float*)d_in[10];
    const float* emi_b     = (const float*)d_in[11];
    const float* bio_emb   = (const float*)d_in[12];
    const float* sel_u_W   = (const float*)d_in[13];
    const float* sel_u_b   = (const float*)d_in[14];
    const float* sel_v_W   = (const float*)d_in[15];
    const float* sel_v_b   = (const float*)d_in[16];
    const float* sel_uv_W  = (const float*)d_in[17];
    const float* sel_uv_b  = (const float*)d_in[18];
    const float* rel_emb   = (const float*)d_in[19];
    const float* crf_start = (const float*)d_in[20];
    const float* crf_end   = (const float*)d_in[21];
    const float* crf_trans = (const float*)d_in[22];
    float* out = (float*)d_out;

    float *p_xg_f, *p_xg_b, *p_u, *p_v, *p_a, *p_cb;
    cudaGetSymbolAddress((void**)&p_xg_f, g_xg_f);
    cudaGetSymbolAddress((void**)&p_xg_b, g_xg_b);
    cudaGetSymbolAddress((void**)&p_u,  g_u);
    cudaGetSymbolAddress((void**)&p_v,  g_v);
    cudaGetSymbolAddress((void**)&p_a,  g_a);
    cudaGetSymbolAddress((void**)&p_cb, g_cb);

    // 0. prep weight slices (k-major, per dir/slice)
    prep_kernel<<<dim3(32, 8, 2), 256>>>(W_hh_f, W_hh_b);

    // 1. input-gate GEMMs: xg = emb @ W_ih^T + b   (M=2048, N=1024, K=256)
    gemm_kernel<<<dim3(16,32), 256>>>(256, 1, nullptr, 0, tokens, word_emb,
        nullptr, nullptr, W_ih_f, 256, b_f, 0, p_xg_f, 1024);
    gemm_kernel<<<dim3(16,32), 256>>>(256, 1, nullptr, 0, tokens, word_emb,
        nullptr, nullptr, W_ih_b, 256, b_b, 0, p_xg_b, 1024);

    // 2. BiLSTM recurrence: 4-batch pipelined clusters (8 x 8 CTAs)
    lstm_cluster_kernel<<<64, 512>>>();

    // 3. o = 0.5*(hf + hb)
    combine_kernel<<<512, 256>>>();

    // 4. CRF loss (per-batch partials)
    crf_kernel<<<16, 128>>>(tokens, bio_gold, emi_W, emi_b,
                            crf_start, crf_end, crf_trans);

    // 5. u/v = relu(oc @ W^T + b)  (M=2048, N=128, K=320)
    gemm_kernel<<<dim3(2,32), 256>>>(320, 2, nullptr, 0, nullptr, nullptr,
        bio_gold, bio_emb, sel_u_W, 320, sel_u_b, 1, p_u, 128);
    gemm_kernel<<<dim3(2,32), 256>>>(320, 2, nullptr, 0, nullptr, nullptr,
        bio_gold, bio_emb, sel_v_W, 320, sel_v_b, 1, p_v, 128);

    // 6. a = u @ W1^T ; cb = v @ W2^T + sel_uv_b  (M=2048, N=128, K=128)
    gemm_kernel<<<dim3(2,32), 256>>>(128, 0, p_u, 128, nullptr, nullptr,
        nullptr, nullptr, sel_uv_W, 256, nullptr, 0, p_a, 128);
    gemm_kernel<<<dim3(2,32), 256>>>(128, 0, p_v, 128, nullptr, nullptr,
        nullptr, nullptr, sel_uv_W + 128, 256, sel_uv_b, 0, p_cb, 128);

    // 7. selection BCE partial sums
    sel_kernel<<<dim3(32,16), 256>>>(rel_emb, sel_gold, tokens);

    // 8. final reduction -> scalar loss
    final_kernel<<<1, 512>>>(tokens, out);
}